// round 16
// baseline (speedup 1.0000x reference)
#include <cuda_runtime.h>
#include <cstdint>

#define CH   256
#define IMG  128
#define HW   (IMG*IMG)
#define BATCH 4
#define HEADS 4
#define NB   16
#define BLK  8
#define HALO 3

__device__ __forceinline__ float tf32r(float x) {
    uint32_t r; asm("cvt.rna.tf32.f32 %0, %1;" : "=r"(r) : "f"(x));
    return __uint_as_float(r);
}
__device__ __forceinline__ void mma8(float* d, uint32_t a0, uint32_t a1,
                                     uint32_t a2, uint32_t a3,
                                     uint32_t b0, uint32_t b1) {
    asm("mma.sync.aligned.m16n8k8.row.col.f32.tf32.tf32.f32 "
        "{%0,%1,%2,%3},{%4,%5,%6,%7},{%8,%9},{%0,%1,%2,%3};"
        : "+f"(d[0]), "+f"(d[1]), "+f"(d[2]), "+f"(d[3])
        : "r"(a0), "r"(a1), "r"(a2), "r"(a3), "r"(b0), "r"(b1));
}
__device__ __forceinline__ void mma16b(float* d, const uint32_t* a,
                                       uint32_t b0, uint32_t b1) {
    asm("mma.sync.aligned.m16n8k16.row.col.f32.bf16.bf16.f32 "
        "{%0,%1,%2,%3},{%4,%5,%6,%7},{%8,%9},{%0,%1,%2,%3};"
        : "+f"(d[0]), "+f"(d[1]), "+f"(d[2]), "+f"(d[3])
        : "r"(a[0]), "r"(a[1]), "r"(a[2]), "r"(a[3]), "r"(b0), "r"(b1));
}
__device__ __forceinline__ void bsplit2(float xe, float xo,
                                        uint32_t& hi, uint32_t& lo) {
    uint32_t h;
    asm("cvt.rn.bf16x2.f32 %0, %1, %2;" : "=r"(h) : "f"(xo), "f"(xe));
    float re = xe - __uint_as_float(h << 16);
    float ro = xo - __uint_as_float(h & 0xffff0000u);
    asm("cvt.rn.bf16x2.f32 %0, %1, %2;" : "=r"(lo) : "f"(ro), "f"(re));
    hi = h;
}

__device__ float g_naux[(long)BATCH*CH*HW];
__device__ float g_q   [(long)BATCH*HW*CH];
__device__ float g_k   [(long)BATCH*HW*CH];
__device__ float g_v   [(long)BATCH*HW*CH];
__device__ float g_wt  [512*256 + 3*256*256];

__global__ void transpose_w(const float* __restrict__ wm,
                            const float* __restrict__ wq,
                            const float* __restrict__ wk,
                            const float* __restrict__ wv,
                            float* __restrict__ wt)
{
    int t = blockIdx.x * 256 + threadIdx.x;
    if (t < 131072)      { int k = t >> 8, o = t & 255; wt[t] = wm[o * 512 + k]; }
    else if (t < 196608) { int u = t - 131072; wt[t] = wq[(u & 255) * 256 + (u >> 8)]; }
    else if (t < 262144) { int u = t - 196608; wt[t] = wk[(u & 255) * 256 + (u >> 8)]; }
    else if (t < 327680) { int u = t - 262144; wt[t] = wv[(u & 255) * 256 + (u >> 8)]; }
}

// ---------------------------------------------------------------------------
// Split-bf16 tensor-core conv GEMM + output-rounding modes:
// mode 0: relu(+bias[m]); 1: *scale; 2: plain; 3: *scale then tf32; 4: tf32.
// ---------------------------------------------------------------------------
__global__ __launch_bounds__(256, 2)
void gemm_b(const float* __restrict__ P,  long pB, int ldP,
            const float* __restrict__ Q0, const float* __restrict__ Q1,
            long qB, int ldQ, int K, int K0,
            float* __restrict__ C, int ldc,
            const float* __restrict__ bias, float scale, int mode, int mswap)
{
    const int tid  = threadIdx.x;
    const int lane = tid & 31, w = tid >> 5;
    const int gid  = lane >> 2, tig = lane & 3;
    const int b    = blockIdx.z;
    const int m0   = (mswap ? blockIdx.x : blockIdx.y) * 128;
    const int n0   = (mswap ? blockIdx.y : blockIdx.x) * 128;
    const float* Pb  = P  + (long)b * pB;
    const float* Q0b = Q0 + (long)b * qB;
    const float* Q1b = Q1 ? (Q1 + (long)b * qB) : nullptr;
    float* Cb = C + (long)b * CH * HW;

    __shared__ uint32_t PH[2][8][136], PL[2][8][136];
    __shared__ uint32_t QH[2][8][136], QL[2][8][136];

    const int side = tid >> 7;
    const int lt   = tid & 127;
    const int k2   = lt >> 4;
    const int mq   = (lt & 15) * 8;

    const int wm = w >> 2, wn = w & 3;
    float Cf[4][4][4];
#pragma unroll
    for (int mt = 0; mt < 4; mt++)
#pragma unroll
        for (int nt = 0; nt < 4; nt++)
#pragma unroll
            for (int q = 0; q < 4; q++) Cf[mt][nt][q] = 0.f;

    const int ntiles = K / 16;
    float4 e0, e1, o0, o1;

    auto loadT = [&](int kb) {
        int kr = kb + 2 * k2;
        if (side == 0) {
            const float* s0 = Pb + (long)kr * ldP + m0 + mq;
            const float* s1 = s0 + ldP;
            e0 = *(const float4*)&s0[0]; e1 = *(const float4*)&s0[4];
            o0 = *(const float4*)&s1[0]; o1 = *(const float4*)&s1[4];
        } else {
            const float* s0 = ((kr     < K0) ? (Q0b + (long)kr * ldQ)
                                             : (Q1b + (long)(kr - K0) * ldQ)) + n0 + mq;
            const float* s1 = ((kr + 1 < K0) ? (Q0b + (long)(kr + 1) * ldQ)
                                             : (Q1b + (long)(kr + 1 - K0) * ldQ)) + n0 + mq;
            e0 = *(const float4*)&s0[0]; e1 = *(const float4*)&s0[4];
            o0 = *(const float4*)&s1[0]; o1 = *(const float4*)&s1[4];
        }
    };
    auto storeT = [&](int buf) {
        float ev[8] = {e0.x,e0.y,e0.z,e0.w,e1.x,e1.y,e1.z,e1.w};
        float ov[8] = {o0.x,o0.y,o0.z,o0.w,o1.x,o1.y,o1.z,o1.w};
        uint32_t hs[8], ls[8];
#pragma unroll
        for (int m = 0; m < 8; m++) bsplit2(ev[m], ov[m], hs[m], ls[m]);
        uint32_t* H = side ? &QH[buf][k2][mq] : &PH[buf][k2][mq];
        uint32_t* L = side ? &QL[buf][k2][mq] : &PL[buf][k2][mq];
        *(uint4*)&H[0] = make_uint4(hs[0], hs[1], hs[2], hs[3]);
        *(uint4*)&H[4] = make_uint4(hs[4], hs[5], hs[6], hs[7]);
        *(uint4*)&L[0] = make_uint4(ls[0], ls[1], ls[2], ls[3]);
        *(uint4*)&L[4] = make_uint4(ls[4], ls[5], ls[6], ls[7]);
    };

    loadT(0); storeT(0);
    __syncthreads();

    for (int kt = 0; kt < ntiles; kt++) {
        const int cur = kt & 1, nxt = cur ^ 1;
        if (kt + 1 < ntiles) loadT((kt + 1) * 16);

        uint32_t bh[4][2], bl[4][2];
#pragma unroll
        for (int nt = 0; nt < 4; nt++) {
            int n = wn * 32 + nt * 8 + gid;
            bh[nt][0] = QH[cur][tig][n];     bh[nt][1] = QH[cur][tig + 4][n];
            bl[nt][0] = QL[cur][tig][n];     bl[nt][1] = QL[cur][tig + 4][n];
        }
#pragma unroll
        for (int mt = 0; mt < 4; mt++) {
            int m = wm * 64 + mt * 16 + gid;
            uint32_t ah[4] = {PH[cur][tig][m], PH[cur][tig][m + 8],
                              PH[cur][tig + 4][m], PH[cur][tig + 4][m + 8]};
            uint32_t al[4] = {PL[cur][tig][m], PL[cur][tig][m + 8],
                              PL[cur][tig + 4][m], PL[cur][tig + 4][m + 8]};
#pragma unroll
            for (int nt = 0; nt < 4; nt++) {
                mma16b(Cf[mt][nt], ah, bh[nt][0], bh[nt][1]);
                mma16b(Cf[mt][nt], ah, bl[nt][0], bl[nt][1]);
                mma16b(Cf[mt][nt], al, bh[nt][0], bh[nt][1]);
            }
        }
        if (kt + 1 < ntiles) { storeT(nxt); __syncthreads(); }
    }

#pragma unroll
    for (int mt = 0; mt < 4; mt++) {
        int r0 = m0 + wm * 64 + mt * 16 + gid;
        float bi0 = 0.f, bi1 = 0.f;
        if (mode == 0) { bi0 = bias[r0]; bi1 = bias[r0 + 8]; }
#pragma unroll
        for (int nt = 0; nt < 4; nt++) {
            int cc = n0 + wn * 32 + nt * 8 + 2 * tig;
            float d0 = Cf[mt][nt][0], d1 = Cf[mt][nt][1];
            float d2 = Cf[mt][nt][2], d3 = Cf[mt][nt][3];
            if (mode == 0) {
                d0 = fmaxf(d0 + bi0, 0.f); d1 = fmaxf(d1 + bi0, 0.f);
                d2 = fmaxf(d2 + bi1, 0.f); d3 = fmaxf(d3 + bi1, 0.f);
            } else if (mode == 1 || mode == 3) {
                d0 *= scale; d1 *= scale; d2 *= scale; d3 *= scale;
            }
            if (mode >= 3) {
                d0 = tf32r(d0); d1 = tf32r(d1); d2 = tf32r(d2); d3 = tf32r(d3);
            }
            *(float2*)&Cb[(long)r0 * ldc + cc]       = make_float2(d0, d1);
            *(float2*)&Cb[(long)(r0 + 8) * ldc + cc] = make_float2(d2, d3);
        }
    }
}

// ---------------------------------------------------------------------------
// Halo attention — pre-rounded Q/V (raw copies) + smem rel tables (FIXED load).
// ---------------------------------------------------------------------------
#define KW_OFF 0
#define KW_STR 68
#define QI_OFF 13600
#define QI_STR 68
#define ST_OFF 0
#define ST_STR 72
#define VJ_OFF 17952
#define VJ_STR 72
#define OT_OFF 0
#define OT_STR 68
#define RED_OFF 32352
#define MX_OFF 32864
#define INV_OFF 32928
#define REL_OFF 32992
#define SM_TOT 33888

__global__ __launch_bounds__(512, 1)
void attn_kernel(const float* __restrict__ gq, const float* __restrict__ gk,
                 const float* __restrict__ gv, const float* __restrict__ relh,
                 const float* __restrict__ relw, float* __restrict__ out)
{
    extern __shared__ float sm[];
    const int tid  = threadIdx.x;
    const int lane = tid & 31, w = tid >> 5;
    const int gid  = lane >> 2, tig = lane & 3;
    const int by = blockIdx.x >> 4, bx = blockIdx.x & 15;
    const int h = blockIdx.y, b = blockIdx.z;
    const int y0 = by * BLK, x0 = bx * BLK;
    const long qbase = (long)b * HW * 256 + h * 64;
    const long obase = ((long)b * CH + h * 64) * HW;

    // rel tables -> smem (relh @REL, relw @REL+448)  [FIXED: strided loop]
    for (int t = tid; t < 896; t += 512)
        sm[REL_OFF + t] = (t < 448) ? relh[t] : relw[t - 448];

    if (tid < 272)      sm[KW_OFF + 196 * KW_STR + tid] = 0.f;
    else if (tid < 560) sm[VJ_OFF + 196 * VJ_STR + (tid - 272)] = 0.f;

    if (tid < 256) {   // Q: pre-rounded in GEMM -> raw copy
        int px = tid >> 2, quad = tid & 3;
        int p = (y0 + (px >> 3)) * IMG + x0 + (px & 7);
        const float* src = gq + qbase + (long)p * 256 + quad * 16;
        float* dst = &sm[QI_OFF + px * QI_STR + quad * 16];
#pragma unroll
        for (int f = 0; f < 4; f++)
            *(float4*)&dst[f * 4] = *(const float4*)(src + f * 4);
    }
    __syncthreads();   // rel tables ready

    for (int u = tid; u < 1568; u += 512) {
        int isV = u >= 784;
        int e = isV ? u - 784 : u;
        int j = e >> 2, quad = e & 3;
        int iw = j / 14, jw = j - iw * 14;
        int yw = y0 - HALO + iw, xw = x0 - HALO + jw;
        bool valid = ((unsigned)yw < IMG) && ((unsigned)xw < IMG);
        int p = valid ? (yw * IMG + xw) : 0;
        if (!isV) {
            const float* src  = gk + qbase + (long)p * 256 + quad * 16;
            const float* bsrc = (quad < 2) ? &sm[REL_OFF + iw * 32 + quad * 16]
                                           : &sm[REL_OFF + 448 + jw * 32 + (quad - 2) * 16];
            float* dst = &sm[KW_OFF + j * KW_STR + quad * 16];
#pragma unroll
            for (int f = 0; f < 4; f++) {
                float4 bv = *(const float4*)(bsrc + f * 4);
                float4 kv = valid ? *(const float4*)(src + f * 4)
                                  : make_float4(0.f, 0.f, 0.f, 0.f);
                *(float4*)&dst[f * 4] =
                    make_float4(tf32r(kv.x + bv.x), tf32r(kv.y + bv.y),
                                tf32r(kv.z + bv.z), tf32r(kv.w + bv.w));
            }
        } else {   // V: pre-rounded in GEMM -> raw copy
            const float* src = gv + qbase + (long)p * 256 + quad * 16;
            float* dst = &sm[VJ_OFF + j * VJ_STR + quad * 16];
#pragma unroll
            for (int f = 0; f < 4; f++)
                *(float4*)&dst[f * 4] = valid ? *(const float4*)(src + f * 4)
                                              : make_float4(0.f, 0.f, 0.f, 0.f);
        }
    }
    __syncthreads();

    // ---- QK^T: 16 warps = 8 m-groups x 2 n-groups (4 n8-tiles each) ---------
    const int wm = w >> 1, wn = w & 1;
    const int mcnt   = (wm < 5) ? 2 : 1;
    const int mtile0 = (wm < 5) ? 2 * wm : 10 + (wm - 5);
    float Cf[2][4][4];
#pragma unroll
    for (int mt = 0; mt < 2; mt++)
#pragma unroll
        for (int nt = 0; nt < 4; nt++)
#pragma unroll
            for (int q = 0; q < 4; q++) Cf[mt][nt][q] = 0.f;

#pragma unroll
    for (int ks = 0; ks < 8; ks++) {
        const int c0 = ks * 8;
        uint32_t Bf[4][2];
#pragma unroll
        for (int nt = 0; nt < 4; nt++) {
            int n = wn * 32 + nt * 8 + gid;
            Bf[nt][0] = __float_as_uint(sm[QI_OFF + n * QI_STR + c0 + tig]);
            Bf[nt][1] = __float_as_uint(sm[QI_OFF + n * QI_STR + c0 + tig + 4]);
        }
#pragma unroll
        for (int mt = 0; mt < 2; mt++) {
            if (mt < mcnt) {
                int r = (mtile0 + mt) * 16 + gid;
                uint32_t a0 = __float_as_uint(sm[KW_OFF + r       * KW_STR + c0 + tig]);
                uint32_t a1 = __float_as_uint(sm[KW_OFF + (r + 8) * KW_STR + c0 + tig]);
                uint32_t a2 = __float_as_uint(sm[KW_OFF + r       * KW_STR + c0 + tig + 4]);
                uint32_t a3 = __float_as_uint(sm[KW_OFF + (r + 8) * KW_STR + c0 + tig + 4]);
#pragma unroll
                for (int nt = 0; nt < 4; nt++)
                    mma8(Cf[mt][nt], a0, a1, a2, a3, Bf[nt][0], Bf[nt][1]);
            }
        }
    }
    __syncthreads();

#pragma unroll
    for (int mt = 0; mt < 2; mt++) {
        if (mt < mcnt) {
#pragma unroll
            for (int nt = 0; nt < 4; nt++) {
                int r = (mtile0 + mt) * 16 + gid;
                int ci = wn * 32 + nt * 8 + 2 * tig;
                *(float2*)&sm[ST_OFF + r * ST_STR + ci] =
                    make_float2(Cf[mt][nt][0], Cf[mt][nt][1]);
                if (r + 8 < 200)
                    *(float2*)&sm[ST_OFF + (r + 8) * ST_STR + ci] =
                        make_float2(Cf[mt][nt][2], Cf[mt][nt][3]);
            }
        }
    }
    __syncthreads();

    {
        const int i = tid & 63, p = tid >> 6;
        const int cnt = (p < 4) ? 25 : 24;
        const int jb  = (p < 4) ? p * 25 : 100 + (p - 4) * 24;
        float m = -1e30f;
        for (int jj = 0; jj < cnt; jj++)
            m = fmaxf(m, sm[ST_OFF + (jb + jj) * ST_STR + i]);
        sm[RED_OFF + p * 64 + i] = m;
        __syncthreads();
        if (tid < 64) {
            float mm = -1e30f;
#pragma unroll
            for (int pp = 0; pp < 8; pp++)
                mm = fmaxf(mm, sm[RED_OFF + pp * 64 + tid]);
            sm[MX_OFF + tid] = mm;
        }
        __syncthreads();
        float mm = sm[MX_OFF + i];
        float s = 0.f;
        for (int jj = 0; jj < cnt; jj++) {
            float e = __expf(sm[ST_OFF + (jb + jj) * ST_STR + i] - mm);
            s += e;
            sm[ST_OFF + (jb + jj) * ST_STR + i] = tf32r(e);
        }
        sm[RED_OFF + p * 64 + i] = s;
        if (tid < 4 * ST_STR) sm[ST_OFF + 196 * ST_STR + tid] = 0.f;
        __syncthreads();
        if (tid < 64) {
            float ss = 0.f;
#pragma unroll
            for (int pp = 0; pp < 8; pp++)
                ss += sm[RED_OFF + pp * 64 + tid];
            sm[INV_OFF + tid] = 1.f / ss;
        }
        __syncthreads();
    }

    {
        const int ibase = (w >> 2) * 16;
        const int wn2 = w & 3;
        float Df[2][4];
#pragma unroll
        for (int nt = 0; nt < 2; nt++)
#pragma unroll
            for (int q = 0; q < 4; q++) Df[nt][q] = 0.f;

        for (int kt = 0; kt < 25; kt++) {
            const int j0 = kt * 8;
            uint32_t a0 = __float_as_uint(sm[ST_OFF + (j0 + tig)     * ST_STR + ibase + gid]);
            uint32_t a1 = __float_as_uint(sm[ST_OFF + (j0 + tig)     * ST_STR + ibase + gid + 8]);
            uint32_t a2 = __float_as_uint(sm[ST_OFF + (j0 + tig + 4) * ST_STR + ibase + gid]);
            uint32_t a3 = __float_as_uint(sm[ST_OFF + (j0 + tig + 4) * ST_STR + ibase + gid + 8]);
#pragma unroll
            for (int nt = 0; nt < 2; nt++) {
                int c0 = wn2 * 16 + nt * 8;
                uint32_t b0 = __float_as_uint(sm[VJ_OFF + (j0 + tig)     * VJ_STR + c0 + gid]);
                uint32_t b1 = __float_as_uint(sm[VJ_OFF + (j0 + tig + 4) * VJ_STR + c0 + gid]);
                mma8(Df[nt], a0, a1, a2, a3, b0, b1);
            }
        }
        float v0 = sm[INV_OFF + ibase + gid];
        float v1 = sm[INV_OFF + ibase + gid + 8];
        __syncthreads();

#pragma unroll
        for (int nt = 0; nt < 2; nt++) {
            int c0 = wn2 * 16 + nt * 8;
            sm[OT_OFF + (c0 + 2*tig    ) * OT_STR + ibase + gid]     = Df[nt][0] * v0;
            sm[OT_OFF + (c0 + 2*tig + 1) * OT_STR + ibase + gid]     = Df[nt][1] * v0;
            sm[OT_OFF + (c0 + 2*tig    ) * OT_STR + ibase + gid + 8] = Df[nt][2] * v1;
            sm[OT_OFF + (c0 + 2*tig + 1) * OT_STR + ibase + gid + 8] = Df[nt][3] * v1;
        }
        __syncthreads();

        int c = tid >> 3, r = tid & 7;
        float4 o0 = *(const float4*)&sm[OT_OFF + c * OT_STR + r * 8];
        float4 o1 = *(const float4*)&sm[OT_OFF + c * OT_STR + r * 8 + 4];
        float* dst = out + obase + (long)c * HW + (y0 + r) * IMG + x0;
        *(float4*)&dst[0] = o0;
        *(float4*)&dst[4] = o1;
    }
}

// ---------------------------------------------------------------------------
extern "C" void kernel_launch(void* const* d_in, const int* in_sizes, int n_in,
                              void* d_out, int out_size)
{
    const float* noisy = (const float*)d_in[0];
    const float* aux   = (const float*)d_in[1];
    const float* w_map = (const float*)d_in[2];
    const float* b_map = (const float*)d_in[3];
    const float* w_q   = (const float*)d_in[4];
    const float* w_k   = (const float*)d_in[5];
    const float* w_v   = (const float*)d_in[6];
    const float* rel_h = (const float*)d_in[7];
    const float* rel_w = (const float*)d_in[8];
    float* out = (float*)d_out;

    float *naux, *q, *k, *v, *wt;
    cudaGetSymbolAddress((void**)&naux, g_naux);
    cudaGetSymbolAddress((void**)&q,    g_q);
    cudaGetSymbolAddress((void**)&k,    g_k);
    cudaGetSymbolAddress((void**)&v,    g_v);
    cudaGetSymbolAddress((void**)&wt,   g_wt);

    transpose_w<<<1280, 256>>>(w_map, w_q, w_k, w_v, wt);

    const long XB = (long)CH * HW;
    dim3 ggrid(128, 2, BATCH);
    gemm_b<<<ggrid, 256>>>(wt, 0, 256, noisy, aux, XB, HW, 512, 256,
                           naux, HW, b_map, 1.f, 0, 0);
    gemm_b<<<ggrid, 256>>>(naux,  XB, HW, wt + 131072, nullptr, 0, 256, 256, 256,
                           q, 256, nullptr, 0.125f, 3, 1);   // scale + tf32 round
    gemm_b<<<ggrid, 256>>>(naux,  XB, HW, wt + 196608, nullptr, 0, 256, 256, 256,
                           k, 256, nullptr, 1.f, 2, 1);      // raw (rounded after bias)
    gemm_b<<<ggrid, 256>>>(noisy, XB, HW, wt + 262144, nullptr, 0, 256, 256, 256,
                           v, 256, nullptr, 1.f, 4, 1);      // tf32 round

    size_t smem = (size_t)SM_TOT * sizeof(float);
    cudaFuncSetAttribute(attn_kernel,
                         cudaFuncAttributeMaxDynamicSharedMemorySize, (int)smem);
    attn_kernel<<<dim3(NB * NB, HEADS, BATCH), 512, smem>>>(q, k, v, rel_h, rel_w, out);
}

// round 17
// speedup vs baseline: 1.0274x; 1.0274x over previous
#include <cuda_runtime.h>
#include <cstdint>

#define CH   256
#define IMG  128
#define HW   (IMG*IMG)
#define BATCH 4
#define HEADS 4
#define NB   16
#define BLK  8
#define HALO 3
#define QKVS 768

__device__ __forceinline__ float tf32r(float x) {
    uint32_t r; asm("cvt.rna.tf32.f32 %0, %1;" : "=r"(r) : "f"(x));
    return __uint_as_float(r);
}
__device__ __forceinline__ void mma8(float* d, uint32_t a0, uint32_t a1,
                                     uint32_t a2, uint32_t a3,
                                     uint32_t b0, uint32_t b1) {
    asm("mma.sync.aligned.m16n8k8.row.col.f32.tf32.tf32.f32 "
        "{%0,%1,%2,%3},{%4,%5,%6,%7},{%8,%9},{%0,%1,%2,%3};"
        : "+f"(d[0]), "+f"(d[1]), "+f"(d[2]), "+f"(d[3])
        : "r"(a0), "r"(a1), "r"(a2), "r"(a3), "r"(b0), "r"(b1));
}
__device__ __forceinline__ void mma16b(float* d, const uint32_t* a,
                                       uint32_t b0, uint32_t b1) {
    asm("mma.sync.aligned.m16n8k16.row.col.f32.bf16.bf16.f32 "
        "{%0,%1,%2,%3},{%4,%5,%6,%7},{%8,%9},{%0,%1,%2,%3};"
        : "+f"(d[0]), "+f"(d[1]), "+f"(d[2]), "+f"(d[3])
        : "r"(a[0]), "r"(a[1]), "r"(a[2]), "r"(a[3]), "r"(b0), "r"(b1));
}
__device__ __forceinline__ void bsplit2(float xe, float xo,
                                        uint32_t& hi, uint32_t& lo) {
    uint32_t h;
    asm("cvt.rn.bf16x2.f32 %0, %1, %2;" : "=r"(h) : "f"(xo), "f"(xe));
    float re = xe - __uint_as_float(h << 16);
    float ro = xo - __uint_as_float(h & 0xffff0000u);
    asm("cvt.rn.bf16x2.f32 %0, %1, %2;" : "=r"(lo) : "f"(ro), "f"(re));
    hi = h;
}

__device__ float g_naux[(long)BATCH*CH*HW];
__device__ float g_qkv [(long)BATCH*HW*QKVS];   // [b][p][q(256)|k(256)|v(256)]
__device__ float g_wt  [512*256 + 3*256*256];

__global__ void transpose_w(const float* __restrict__ wm,
                            const float* __restrict__ wq,
                            const float* __restrict__ wk,
                            const float* __restrict__ wv,
                            float* __restrict__ wt)
{
    int t = blockIdx.x * 256 + threadIdx.x;
    if (t < 131072)      { int k = t >> 8, o = t & 255; wt[t] = wm[o * 512 + k]; }
    else if (t < 196608) { int u = t - 131072; wt[t] = wq[(u & 255) * 256 + (u >> 8)]; }
    else if (t < 262144) { int u = t - 196608; wt[t] = wk[(u & 255) * 256 + (u >> 8)]; }
    else if (t < 327680) { int u = t - 262144; wt[t] = wv[(u & 255) * 256 + (u >> 8)]; }
}

// ---------------------------------------------------------------------------
// Split-bf16 GEMM for naux (c-major out) — R14-proven.
// ---------------------------------------------------------------------------
__global__ __launch_bounds__(256, 2)
void gemm_naux(const float* __restrict__ Wt,
               const float* __restrict__ X0, const float* __restrict__ X1,
               float* __restrict__ C, const float* __restrict__ bias)
{
    const int tid  = threadIdx.x;
    const int lane = tid & 31, w = tid >> 5;
    const int gid  = lane >> 2, tig = lane & 3;
    const int b    = blockIdx.z;
    const int n0   = blockIdx.x * 128;     // pixels
    const int m0   = blockIdx.y * 128;     // out channels
    const long XB  = (long)CH * HW;
    const float* X0b = X0 + b * XB;
    const float* X1b = X1 + b * XB;
    float* Cb = C + b * XB;

    __shared__ uint32_t PH[2][8][136], PL[2][8][136];
    __shared__ uint32_t QH[2][8][136], QL[2][8][136];

    const int side = tid >> 7;
    const int lt   = tid & 127;
    const int k2   = lt >> 4;
    const int mq   = (lt & 15) * 8;

    const int wm = w >> 2, wn = w & 3;
    float Cf[4][4][4];
#pragma unroll
    for (int mt = 0; mt < 4; mt++)
#pragma unroll
        for (int nt = 0; nt < 4; nt++)
#pragma unroll
            for (int q = 0; q < 4; q++) Cf[mt][nt][q] = 0.f;

    float4 e0, e1, o0, o1;
    auto loadT = [&](int kb) {
        int kr = kb + 2 * k2;
        if (side == 0) {   // P = wmapT [512][256]
            const float* s0 = Wt + (long)kr * 256 + m0 + mq;
            e0 = *(const float4*)&s0[0];   e1 = *(const float4*)&s0[4];
            o0 = *(const float4*)&s0[256]; o1 = *(const float4*)&s0[260];
        } else {           // Q = concat(noisy, aux) c-major
            const float* s0 = ((kr     < 256) ? (X0b + (long)kr * HW)
                                              : (X1b + (long)(kr - 256) * HW)) + n0 + mq;
            const float* s1 = ((kr + 1 < 256) ? (X0b + (long)(kr + 1) * HW)
                                              : (X1b + (long)(kr + 1 - 256) * HW)) + n0 + mq;
            e0 = *(const float4*)&s0[0]; e1 = *(const float4*)&s0[4];
            o0 = *(const float4*)&s1[0]; o1 = *(const float4*)&s1[4];
        }
    };
    auto storeT = [&](int buf) {
        float ev[8] = {e0.x,e0.y,e0.z,e0.w,e1.x,e1.y,e1.z,e1.w};
        float ov[8] = {o0.x,o0.y,o0.z,o0.w,o1.x,o1.y,o1.z,o1.w};
        uint32_t hs[8], ls[8];
#pragma unroll
        for (int m = 0; m < 8; m++) bsplit2(ev[m], ov[m], hs[m], ls[m]);
        uint32_t* H = side ? &QH[buf][k2][mq] : &PH[buf][k2][mq];
        uint32_t* L = side ? &QL[buf][k2][mq] : &PL[buf][k2][mq];
        *(uint4*)&H[0] = make_uint4(hs[0], hs[1], hs[2], hs[3]);
        *(uint4*)&H[4] = make_uint4(hs[4], hs[5], hs[6], hs[7]);
        *(uint4*)&L[0] = make_uint4(ls[0], ls[1], ls[2], ls[3]);
        *(uint4*)&L[4] = make_uint4(ls[4], ls[5], ls[6], ls[7]);
    };

    loadT(0); storeT(0);
    __syncthreads();

    for (int kt = 0; kt < 32; kt++) {
        const int cur = kt & 1, nxt = cur ^ 1;
        if (kt + 1 < 32) loadT((kt + 1) * 16);

        uint32_t bh[4][2], bl[4][2];
#pragma unroll
        for (int nt = 0; nt < 4; nt++) {
            int n = wn * 32 + nt * 8 + gid;
            bh[nt][0] = QH[cur][tig][n]; bh[nt][1] = QH[cur][tig + 4][n];
            bl[nt][0] = QL[cur][tig][n]; bl[nt][1] = QL[cur][tig + 4][n];
        }
#pragma unroll
        for (int mt = 0; mt < 4; mt++) {
            int m = wm * 64 + mt * 16 + gid;
            uint32_t ah[4] = {PH[cur][tig][m], PH[cur][tig][m + 8],
                              PH[cur][tig + 4][m], PH[cur][tig + 4][m + 8]};
            uint32_t al[4] = {PL[cur][tig][m], PL[cur][tig][m + 8],
                              PL[cur][tig + 4][m], PL[cur][tig + 4][m + 8]};
#pragma unroll
            for (int nt = 0; nt < 4; nt++) {
                mma16b(Cf[mt][nt], ah, bh[nt][0], bh[nt][1]);
                mma16b(Cf[mt][nt], ah, bl[nt][0], bl[nt][1]);
                mma16b(Cf[mt][nt], al, bh[nt][0], bh[nt][1]);
            }
        }
        if (kt + 1 < 32) { storeT(nxt); __syncthreads(); }
    }

#pragma unroll
    for (int mt = 0; mt < 4; mt++) {
        int r0 = m0 + wm * 64 + mt * 16 + gid;
        float bi0 = bias[r0], bi1 = bias[r0 + 8];
#pragma unroll
        for (int nt = 0; nt < 4; nt++) {
            int cc = n0 + wn * 32 + nt * 8 + 2 * tig;
            float d0 = fmaxf(Cf[mt][nt][0] + bi0, 0.f);
            float d1 = fmaxf(Cf[mt][nt][1] + bi0, 0.f);
            float d2 = fmaxf(Cf[mt][nt][2] + bi1, 0.f);
            float d3 = fmaxf(Cf[mt][nt][3] + bi1, 0.f);
            *(float2*)&Cb[(long)r0 * HW + cc]       = make_float2(d0, d1);
            *(float2*)&Cb[(long)(r0 + 8) * HW + cc] = make_float2(d2, d3);
        }
    }
}

// ---------------------------------------------------------------------------
// Merged q/k/v GEMM -> qkv[b][p][768]. blockIdx.y: slab = y>>1 (0=q,1=k,2=v),
// half = y&1 (which 128 of the 256 output channels).
// ---------------------------------------------------------------------------
__global__ __launch_bounds__(256, 2)
void gemm_qkv(const float* __restrict__ naux, const float* __restrict__ noisy,
              const float* __restrict__ wt, float* __restrict__ qkv)
{
    const int tid  = threadIdx.x;
    const int lane = tid & 31, w = tid >> 5;
    const int gid  = lane >> 2, tig = lane & 3;
    const int b    = blockIdx.z;
    const int m0   = blockIdx.x * 128;            // pixels
    const int slab = blockIdx.y >> 1;             // 0=q, 1=k, 2=v
    const int nw0  = (blockIdx.y & 1) * 128;      // weight column offset
    const int co0  = slab * 256 + nw0;            // output column offset
    const float scl = (slab == 0) ? 0.125f : 1.f;
    const long XB = (long)CH * HW;
    const float* Pb = ((slab == 2) ? noisy : naux) + b * XB;   // c-major pixels
    const float* Wb = wt + 131072 + slab * 65536;              // k-major weights
    float* Cb = qkv + (long)b * HW * QKVS;

    __shared__ uint32_t PH[2][8][136], PL[2][8][136];
    __shared__ uint32_t QH[2][8][136], QL[2][8][136];

    const int side = tid >> 7;
    const int lt   = tid & 127;
    const int k2   = lt >> 4;
    const int mq   = (lt & 15) * 8;

    const int wm = w >> 2, wn = w & 3;
    float Cf[4][4][4];
#pragma unroll
    for (int mt = 0; mt < 4; mt++)
#pragma unroll
        for (int nt = 0; nt < 4; nt++)
#pragma unroll
            for (int q = 0; q < 4; q++) Cf[mt][nt][q] = 0.f;

    float4 e0, e1, o0, o1;
    auto loadT = [&](int kb) {
        int kr = kb + 2 * k2;
        if (side == 0) {   // P = pixel operand, c-major (ld = HW)
            const float* s0 = Pb + (long)kr * HW + m0 + mq;
            const float* s1 = s0 + HW;
            e0 = *(const float4*)&s0[0]; e1 = *(const float4*)&s0[4];
            o0 = *(const float4*)&s1[0]; o1 = *(const float4*)&s1[4];
        } else {           // Q = weights (ld = 256)
            const float* s0 = Wb + (long)kr * 256 + nw0 + mq;
            e0 = *(const float4*)&s0[0];   e1 = *(const float4*)&s0[4];
            o0 = *(const float4*)&s0[256]; o1 = *(const float4*)&s0[260];
        }
    };
    auto storeT = [&](int buf) {
        float ev[8] = {e0.x,e0.y,e0.z,e0.w,e1.x,e1.y,e1.z,e1.w};
        float ov[8] = {o0.x,o0.y,o0.z,o0.w,o1.x,o1.y,o1.z,o1.w};
        uint32_t hs[8], ls[8];
#pragma unroll
        for (int m = 0; m < 8; m++) bsplit2(ev[m], ov[m], hs[m], ls[m]);
        uint32_t* H = side ? &QH[buf][k2][mq] : &PH[buf][k2][mq];
        uint32_t* L = side ? &QL[buf][k2][mq] : &PL[buf][k2][mq];
        *(uint4*)&H[0] = make_uint4(hs[0], hs[1], hs[2], hs[3]);
        *(uint4*)&H[4] = make_uint4(hs[4], hs[5], hs[6], hs[7]);
        *(uint4*)&L[0] = make_uint4(ls[0], ls[1], ls[2], ls[3]);
        *(uint4*)&L[4] = make_uint4(ls[4], ls[5], ls[6], ls[7]);
    };

    loadT(0); storeT(0);
    __syncthreads();

    for (int kt = 0; kt < 16; kt++) {
        const int cur = kt & 1, nxt = cur ^ 1;
        if (kt + 1 < 16) loadT((kt + 1) * 16);

        uint32_t bh[4][2], bl[4][2];
#pragma unroll
        for (int nt = 0; nt < 4; nt++) {
            int n = wn * 32 + nt * 8 + gid;
            bh[nt][0] = QH[cur][tig][n]; bh[nt][1] = QH[cur][tig + 4][n];
            bl[nt][0] = QL[cur][tig][n]; bl[nt][1] = QL[cur][tig + 4][n];
        }
#pragma unroll
        for (int mt = 0; mt < 4; mt++) {
            int m = wm * 64 + mt * 16 + gid;
            uint32_t ah[4] = {PH[cur][tig][m], PH[cur][tig][m + 8],
                              PH[cur][tig + 4][m], PH[cur][tig + 4][m + 8]};
            uint32_t al[4] = {PL[cur][tig][m], PL[cur][tig][m + 8],
                              PL[cur][tig + 4][m], PL[cur][tig + 4][m + 8]};
#pragma unroll
            for (int nt = 0; nt < 4; nt++) {
                mma16b(Cf[mt][nt], ah, bh[nt][0], bh[nt][1]);
                mma16b(Cf[mt][nt], ah, bl[nt][0], bl[nt][1]);
                mma16b(Cf[mt][nt], al, bh[nt][0], bh[nt][1]);
            }
        }
        if (kt + 1 < 16) { storeT(nxt); __syncthreads(); }
    }

#pragma unroll
    for (int mt = 0; mt < 4; mt++) {
        int r0 = m0 + wm * 64 + mt * 16 + gid;      // pixel
#pragma unroll
        for (int nt = 0; nt < 4; nt++) {
            int cc = co0 + wn * 32 + nt * 8 + 2 * tig;
            float d0 = Cf[mt][nt][0] * scl, d1 = Cf[mt][nt][1] * scl;
            float d2 = Cf[mt][nt][2] * scl, d3 = Cf[mt][nt][3] * scl;
            *(float2*)&Cb[(long)r0 * QKVS + cc]       = make_float2(d0, d1);
            *(float2*)&Cb[(long)(r0 + 8) * QKVS + cc] = make_float2(d2, d3);
        }
    }
}

// ---------------------------------------------------------------------------
// Halo attention — R14 structure, qkv-packed input, fused K/V gather loop.
// ---------------------------------------------------------------------------
#define KW_OFF 0
#define KW_STR 68
#define QI_OFF 13600
#define QI_STR 68
#define ST_OFF 0
#define ST_STR 72
#define VJ_OFF 17952
#define VJ_STR 72
#define OT_OFF 0
#define OT_STR 68
#define RED_OFF 32352
#define MX_OFF 32864
#define INV_OFF 32928
#define SM_TOT 32992

__global__ __launch_bounds__(512, 1)
void attn_kernel(const float* __restrict__ qkv, const float* __restrict__ relh,
                 const float* __restrict__ relw, float* __restrict__ out)
{
    extern __shared__ float sm[];
    const int tid  = threadIdx.x;
    const int lane = tid & 31, w = tid >> 5;
    const int gid  = lane >> 2, tig = lane & 3;
    const int by = blockIdx.x >> 4, bx = blockIdx.x & 15;
    const int h = blockIdx.y, b = blockIdx.z;
    const int y0 = by * BLK, x0 = bx * BLK;
    const long qbase = (long)b * HW * QKVS + h * 64;
    const long obase = ((long)b * CH + h * 64) * HW;

    if (tid < 272)      sm[KW_OFF + 196 * KW_STR + tid] = 0.f;
    else if (tid < 560) sm[VJ_OFF + 196 * VJ_STR + (tid - 272)] = 0.f;

    if (tid < 256) {   // Q
        int px = tid >> 2, quad = tid & 3;
        int p = (y0 + (px >> 3)) * IMG + x0 + (px & 7);
        const float* src = qkv + qbase + (long)p * QKVS + quad * 16;
        float* dst = &sm[QI_OFF + px * QI_STR + quad * 16];
#pragma unroll
        for (int f = 0; f < 4; f++) {
            float4 v = *(const float4*)(src + f * 4);
            *(float4*)&dst[f * 4] = make_float4(tf32r(v.x), tf32r(v.y),
                                                tf32r(v.z), tf32r(v.w));
        }
    }
    // fused K+V gather: one index computation per (j, quad)
    for (int u = tid; u < 784; u += 512) {
        int j = u >> 2, quad = u & 3;
        int iw = j / 14, jw = j - iw * 14;
        int yw = y0 - HALO + iw, xw = x0 - HALO + jw;
        bool valid = ((unsigned)yw < IMG) && ((unsigned)xw < IMG);
        int p = valid ? (yw * IMG + xw) : 0;
        const float* ksrc = qkv + qbase + (long)p * QKVS + 256 + quad * 16;
        const float* vsrc = ksrc + 256;
        const float* bsrc = (quad < 2) ? (relh + iw * 32 + quad * 16)
                                       : (relw + jw * 32 + (quad - 2) * 16);
        float* kdst = &sm[KW_OFF + j * KW_STR + quad * 16];
        float* vdst = &sm[VJ_OFF + j * VJ_STR + quad * 16];
#pragma unroll
        for (int f = 0; f < 4; f++) {
            float4 bv = *(const float4*)(bsrc + f * 4);
            float4 kv = valid ? *(const float4*)(ksrc + f * 4)
                              : make_float4(0.f, 0.f, 0.f, 0.f);
            float4 vv = valid ? *(const float4*)(vsrc + f * 4)
                              : make_float4(0.f, 0.f, 0.f, 0.f);
            *(float4*)&kdst[f * 4] =
                make_float4(tf32r(kv.x + bv.x), tf32r(kv.y + bv.y),
                            tf32r(kv.z + bv.z), tf32r(kv.w + bv.w));
            *(float4*)&vdst[f * 4] =
                make_float4(tf32r(vv.x), tf32r(vv.y), tf32r(vv.z), tf32r(vv.w));
        }
    }
    __syncthreads();

    // ---- QK^T: 16 warps = 8 m-groups x 2 n-groups ---------------------------
    const int wm = w >> 1, wn = w & 1;
    const int mcnt   = (wm < 5) ? 2 : 1;
    const int mtile0 = (wm < 5) ? 2 * wm : 10 + (wm - 5);
    float Cf[2][4][4];
#pragma unroll
    for (int mt = 0; mt < 2; mt++)
#pragma unroll
        for (int nt = 0; nt < 4; nt++)
#pragma unroll
            for (int q = 0; q < 4; q++) Cf[mt][nt][q] = 0.f;

#pragma unroll
    for (int ks = 0; ks < 8; ks++) {
        const int c0 = ks * 8;
        uint32_t Bf[4][2];
#pragma unroll
        for (int nt = 0; nt < 4; nt++) {
            int n = wn * 32 + nt * 8 + gid;
            Bf[nt][0] = __float_as_uint(sm[QI_OFF + n * QI_STR + c0 + tig]);
            Bf[nt][1] = __float_as_uint(sm[QI_OFF + n * QI_STR + c0 + tig + 4]);
        }
#pragma unroll
        for (int mt = 0; mt < 2; mt++) {
            if (mt < mcnt) {
                int r = (mtile0 + mt) * 16 + gid;
                uint32_t a0 = __float_as_uint(sm[KW_OFF + r       * KW_STR + c0 + tig]);
                uint32_t a1 = __float_as_uint(sm[KW_OFF + (r + 8) * KW_STR + c0 + tig]);
                uint32_t a2 = __float_as_uint(sm[KW_OFF + r       * KW_STR + c0 + tig + 4]);
                uint32_t a3 = __float_as_uint(sm[KW_OFF + (r + 8) * KW_STR + c0 + tig + 4]);
#pragma unroll
                for (int nt = 0; nt < 4; nt++)
                    mma8(Cf[mt][nt], a0, a1, a2, a3, Bf[nt][0], Bf[nt][1]);
            }
        }
    }
    __syncthreads();

#pragma unroll
    for (int mt = 0; mt < 2; mt++) {
        if (mt < mcnt) {
#pragma unroll
            for (int nt = 0; nt < 4; nt++) {
                int r = (mtile0 + mt) * 16 + gid;
                int ci = wn * 32 + nt * 8 + 2 * tig;
                *(float2*)&sm[ST_OFF + r * ST_STR + ci] =
                    make_float2(Cf[mt][nt][0], Cf[mt][nt][1]);
                if (r + 8 < 200)
                    *(float2*)&sm[ST_OFF + (r + 8) * ST_STR + ci] =
                        make_float2(Cf[mt][nt][2], Cf[mt][nt][3]);
            }
        }
    }
    __syncthreads();

    {
        const int i = tid & 63, p = tid >> 6;
        const int cnt = (p < 4) ? 25 : 24;
        const int jb  = (p < 4) ? p * 25 : 100 + (p - 4) * 24;
        float m = -1e30f;
        for (int jj = 0; jj < cnt; jj++)
            m = fmaxf(m, sm[ST_OFF + (jb + jj) * ST_STR + i]);
        sm[RED_OFF + p * 64 + i] = m;
        __syncthreads();
        if (tid < 64) {
            float mm = -1e30f;
#pragma unroll
            for (int pp = 0; pp < 8; pp++)
                mm = fmaxf(mm, sm[RED_OFF + pp * 64 + tid]);
            sm[MX_OFF + tid] = mm;
        }
        __syncthreads();
        float mm = sm[MX_OFF + i];
        float s = 0.f;
        for (int jj = 0; jj < cnt; jj++) {
            float e = __expf(sm[ST_OFF + (jb + jj) * ST_STR + i] - mm);
            s += e;
            sm[ST_OFF + (jb + jj) * ST_STR + i] = tf32r(e);
        }
        sm[RED_OFF + p * 64 + i] = s;
        if (tid < 4 * ST_STR) sm[ST_OFF + 196 * ST_STR + tid] = 0.f;
        __syncthreads();
        if (tid < 64) {
            float ss = 0.f;
#pragma unroll
            for (int pp = 0; pp < 8; pp++)
                ss += sm[RED_OFF + pp * 64 + tid];
            sm[INV_OFF + tid] = 1.f / ss;
        }
        __syncthreads();
    }

    {
        const int ibase = (w >> 2) * 16;
        const int wn2 = w & 3;
        float Df[2][4];
#pragma unroll
        for (int nt = 0; nt < 2; nt++)
#pragma unroll
            for (int q = 0; q < 4; q++) Df[nt][q] = 0.f;

        for (int kt = 0; kt < 25; kt++) {
            const int j0 = kt * 8;
            uint32_t a0 = __float_as_uint(sm[ST_OFF + (j0 + tig)     * ST_STR + ibase + gid]);
            uint32_t a1 = __float_as_uint(sm[ST_OFF + (j0 + tig)     * ST_STR + ibase + gid + 8]);
            uint32_t a2 = __float_as_uint(sm[ST_OFF + (j0 + tig + 4) * ST_STR + ibase + gid]);
            uint32_t a3 = __float_as_uint(sm[ST_OFF + (j0 + tig + 4) * ST_STR + ibase + gid + 8]);
#pragma unroll
            for (int nt = 0; nt < 2; nt++) {
                int c0 = wn2 * 16 + nt * 8;
                uint32_t b0 = __float_as_uint(sm[VJ_OFF + (j0 + tig)     * VJ_STR + c0 + gid]);
                uint32_t b1 = __float_as_uint(sm[VJ_OFF + (j0 + tig + 4) * VJ_STR + c0 + gid]);
                mma8(Df[nt], a0, a1, a2, a3, b0, b1);
            }
        }
        float v0 = sm[INV_OFF + ibase + gid];
        float v1 = sm[INV_OFF + ibase + gid + 8];
        __syncthreads();

#pragma unroll
        for (int nt = 0; nt < 2; nt++) {
            int c0 = wn2 * 16 + nt * 8;
            sm[OT_OFF + (c0 + 2*tig    ) * OT_STR + ibase + gid]     = Df[nt][0] * v0;
            sm[OT_OFF + (c0 + 2*tig + 1) * OT_STR + ibase + gid]     = Df[nt][1] * v0;
            sm[OT_OFF + (c0 + 2*tig    ) * OT_STR + ibase + gid + 8] = Df[nt][2] * v1;
            sm[OT_OFF + (c0 + 2*tig + 1) * OT_STR + ibase + gid + 8] = Df[nt][3] * v1;
        }
        __syncthreads();

        int c = tid >> 3, r = tid & 7;
        float4 o0 = *(const float4*)&sm[OT_OFF + c * OT_STR + r * 8];
        float4 o1 = *(const float4*)&sm[OT_OFF + c * OT_STR + r * 8 + 4];
        float* dst = out + obase + (long)c * HW + (y0 + r) * IMG + x0;
        *(float4*)&dst[0] = o0;
        *(float4*)&dst[4] = o1;
    }
}

// ---------------------------------------------------------------------------
extern "C" void kernel_launch(void* const* d_in, const int* in_sizes, int n_in,
                              void* d_out, int out_size)
{
    const float* noisy = (const float*)d_in[0];
    const float* aux   = (const float*)d_in[1];
    const float* w_map = (const float*)d_in[2];
    const float* b_map = (const float*)d_in[3];
    const float* w_q   = (const float*)d_in[4];
    const float* w_k   = (const float*)d_in[5];
    const float* w_v   = (const float*)d_in[6];
    const float* rel_h = (const float*)d_in[7];
    const float* rel_w = (const float*)d_in[8];
    float* out = (float*)d_out;

    float *naux, *qkv, *wt;
    cudaGetSymbolAddress((void**)&naux, g_naux);
    cudaGetSymbolAddress((void**)&qkv,  g_qkv);
    cudaGetSymbolAddress((void**)&wt,   g_wt);

    transpose_w<<<1280, 256>>>(w_map, w_q, w_k, w_v, wt);

    gemm_naux<<<dim3(128, 2, BATCH), 256>>>(wt, noisy, aux, naux, b_map);
    gemm_qkv<<<dim3(128, 6, BATCH), 256>>>(naux, noisy, wt, qkv);

    size_t smem = (size_t)SM_TOT * sizeof(float);
    cudaFuncSetAttribute(attn_kernel,
                         cudaFuncAttributeMaxDynamicSharedMemorySize, (int)smem);
    attn_kernel<<<dim3(NB * NB, HEADS, BATCH), 512, smem>>>(qkv, rel_h, rel_w, out);
}